// round 16
// baseline (speedup 1.0000x reference)
#include <cuda_runtime.h>
#include <cstdint>

#define HH 64
#define WW 64
#define HW 4096
#define CCH 256
#define NK 33

// Scratch
__device__ float g_G[2u * 256u * 4096u];  // G[b][d][p] = Mt @ Fte + u
__device__ float g_M[256u * 256u];        // Mt[d][c]
__device__ float g_u[256u];               // u[d]
__device__ unsigned g_gate = 0u;
__device__ unsigned g_done = 0u;

// ---------------------------------------------------------------------------
// f32x2 packed helpers (FFMA2 via PTX fma.rn.f32x2) — used by attn phase B.
// ---------------------------------------------------------------------------
__device__ __forceinline__ unsigned long long pack2_bcast(float x) {
  unsigned long long r;
  asm("mov.b64 %0, {%1, %1};" : "=l"(r) : "f"(x));
  return r;
}
__device__ __forceinline__ unsigned long long ffma2(unsigned long long a,
                                                    unsigned long long b,
                                                    unsigned long long c) {
  unsigned long long d;
  asm("fma.rn.f32x2 %0, %1, %2, %3;" : "=l"(d) : "l"(a), "l"(b), "l"(c));
  return d;
}
__device__ __forceinline__ void unpack2(unsigned long long v, float& lo, float& hi) {
  asm("mov.b64 {%0, %1}, %2;" : "=f"(lo), "=f"(hi) : "l"(v));
}

// ---------------------------------------------------------------------------
// tf32 helpers (baseline sm_80 PTX — NOT arch-'a'-gated)
// ---------------------------------------------------------------------------
__device__ __forceinline__ uint32_t f2tf32(float x) {
  uint32_t r;
  asm("cvt.rna.tf32.f32 %0, %1;" : "=r"(r) : "f"(x));
  return r;
}
// D(16x8) += A(16x8, row) * B(8x8, col);  a,b are tf32 in b32 regs.
__device__ __forceinline__ void mma_tf32(float* d, const uint32_t* a,
                                         const uint32_t* b) {
  asm volatile(
      "mma.sync.aligned.m16n8k8.row.col.f32.tf32.tf32.f32 "
      "{%0,%1,%2,%3},{%4,%5,%6,%7},{%8,%9},{%0,%1,%2,%3};"
      : "+f"(d[0]), "+f"(d[1]), "+f"(d[2]), "+f"(d[3])
      : "r"(a[0]), "r"(a[1]), "r"(a[2]), "r"(a[3]), "r"(b[0]), "r"(b[1]));
}

// ---------------------------------------------------------------------------
// Kernel 1 (fused): prep (Mt, u) + G = Mt @ Fte + u via tf32 mma (3xTF32).
// 256 CTAs, tile 128o x 64p, 2 CTAs/SM. Prep phase identical to R15.
// ---------------------------------------------------------------------------
#define PSTR 36
#define FUSED_SMEM (2 * 256 * PSTR * (int)sizeof(float))  // 73728 B

__global__ __launch_bounds__(256, 2) void psla_gemm_fused(
    const float* __restrict__ Fte, const float* __restrict__ Wf,
    const float* __restrict__ Wg, const float* __restrict__ bg) {
  extern __shared__ float dsm[];
  const int bid = blockIdx.x;
  const int tid = threadIdx.x;

  // ===== Phase 0: prep (first 65 CTAs) =====
  if (bid < 64) {
    float (*sg)[PSTR] = (float (*)[PSTR])dsm;
    float (*sf)[PSTR] = (float (*)[PSTR])(dsm + 256 * PSTR);
    const int c0 = (bid & 7) * 32;
    const int d0 = (bid >> 3) * 32;

    float4 ga[8], fa[8];
#pragma unroll
    for (int j = 0; j < 8; j++) {
      ga[j] = *(const float4*)(Wg + (size_t)tid * 256 + c0 + 4 * j);
      fa[j] = *(const float4*)(Wf + (size_t)tid * 256 + d0 + 4 * j);
    }
#pragma unroll
    for (int j = 0; j < 8; j++) {
      *(float4*)&sg[tid][4 * j] = ga[j];
      *(float4*)&sf[tid][4 * j] = fa[j];
    }
    __syncthreads();

    const int tc = (tid & 15) * 2, td = (tid >> 4) * 2;
    float a00 = 0.f, a01 = 0.f, a10 = 0.f, a11 = 0.f;
#pragma unroll 8
    for (int kk = 0; kk < 256; kk++) {
      const float2 g2 = *(const float2*)&sg[kk][tc];
      const float2 f2 = *(const float2*)&sf[kk][td];
      a00 = fmaf(f2.x, g2.x, a00);
      a01 = fmaf(f2.x, g2.y, a01);
      a10 = fmaf(f2.y, g2.x, a10);
      a11 = fmaf(f2.y, g2.y, a11);
    }
    g_M[(size_t)(d0 + td + 0) * 256 + c0 + tc + 0] = a00;
    g_M[(size_t)(d0 + td + 0) * 256 + c0 + tc + 1] = a01;
    g_M[(size_t)(d0 + td + 1) * 256 + c0 + tc + 0] = a10;
    g_M[(size_t)(d0 + td + 1) * 256 + c0 + tc + 1] = a11;

    __threadfence();
    __syncthreads();
    if (tid == 0) atomicAdd(&g_gate, 1u);
  } else if (bid == 64) {
    float s0 = 0.f, s1 = 0.f, s2 = 0.f, s3 = 0.f;
#pragma unroll
    for (int o = 0; o < 256; o += 4) {
      s0 = fmaf(bg[o + 0], Wf[(o + 0) * 256 + tid], s0);
      s1 = fmaf(bg[o + 1], Wf[(o + 1) * 256 + tid], s1);
      s2 = fmaf(bg[o + 2], Wf[(o + 2) * 256 + tid], s2);
      s3 = fmaf(bg[o + 3], Wf[(o + 3) * 256 + tid], s3);
    }
    g_u[tid] = (s0 + s1) + (s2 + s3);
    __threadfence();
    __syncthreads();
    if (tid == 0) atomicAdd(&g_gate, 1u);
  }

  // ===== Gate =====
  if (tid == 0) {
    while (atomicAdd(&g_gate, 0u) < 65u) __nanosleep(64);
  }
  __syncthreads();

  // ===== Phase 1: tf32 mma GEMM, tile 128o x 64p, kc=32 =====
  {
    uint32_t* sAh = (uint32_t*)dsm;     // [4 ks][128 o][9]
    uint32_t* sAl = sAh + 4608;
    uint32_t* sBh = sAl + 4608;         // [4 ks][64 p][9]
    uint32_t* sBl = sBh + 2304;         // total 13824 u32 = 55296 B

    const int rest = bid >> 6;
    const int b = rest & 1;
    const int o0 = (rest >> 1) * 128;
    const int p0 = (bid & 63) * 64;
    const float* X = Fte + (size_t)b * CCH * HW;
    float* Go = g_G + (size_t)b * CCH * HW;

    const int lane = tid & 31;
    const int wrp = tid >> 5;
    const int wm = wrp & 3, wn = wrp >> 2;  // 4 m-warps x 2 n-warps
    const int g = lane >> 2, tq = lane & 3;

    const int ao = tid >> 1, akg = (tid & 1) * 16;  // A loader
    const int bk = tid >> 3, bp = (tid & 7) * 8;    // B loader
    const int bks = bk >> 3, bkr = bk & 7;

    float d[2][4][4];
#pragma unroll
    for (int i = 0; i < 2; i++)
#pragma unroll
      for (int j = 0; j < 4; j++)
#pragma unroll
        for (int r = 0; r < 4; r++) d[i][j][r] = 0.f;

    for (int chunk = 0; chunk < 8; chunk++) {
      const int k0 = chunk * 32;
      float4 av[4];
#pragma unroll
      for (int j = 0; j < 4; j++)
        av[j] =
            *(const float4*)(g_M + (size_t)(o0 + ao) * CCH + k0 + akg + 4 * j);
      const float4 bv0 = *(const float4*)(X + (size_t)(k0 + bk) * HW + p0 + bp);
      const float4 bv1 =
          *(const float4*)(X + (size_t)(k0 + bk) * HW + p0 + bp + 4);

      __syncthreads();  // previous chunk's mma done reading smem

      // A: hi/lo split, store at [ks][o][kr] (stride 9 -> STS conflict-free)
#pragma unroll
      for (int j = 0; j < 4; j++) {
        const float xs[4] = {av[j].x, av[j].y, av[j].z, av[j].w};
#pragma unroll
        for (int e = 0; e < 4; e++) {
          const int kk = akg + 4 * j + e;
          const int pos = ((kk >> 3) * 128 + ao) * 9 + (kk & 7);
          const uint32_t hi = f2tf32(xs[e]);
          sAh[pos] = hi;
          sAl[pos] = f2tf32(xs[e] - __uint_as_float(hi));
        }
      }
      // B: store at [ks][p][kr]
      {
        const float xs[8] = {bv0.x, bv0.y, bv0.z, bv0.w,
                             bv1.x, bv1.y, bv1.z, bv1.w};
#pragma unroll
        for (int j = 0; j < 8; j++) {
          const int pos = (bks * 64 + bp + j) * 9 + bkr;
          const uint32_t hi = f2tf32(xs[j]);
          sBh[pos] = hi;
          sBl[pos] = f2tf32(xs[j] - __uint_as_float(hi));
        }
      }
      __syncthreads();

#pragma unroll
      for (int ks = 0; ks < 4; ks++) {
        const int abase = ks * 128 * 9;
        const int bbase = ks * 64 * 9;
        uint32_t ah[2][4], al[2][4];
#pragma unroll
        for (int mi = 0; mi < 2; mi++) {
          const int r0 = abase + (wm * 32 + mi * 16 + g) * 9;
          const int r1 = r0 + 8 * 9;
          ah[mi][0] = sAh[r0 + tq];      // (row g,    k t)
          ah[mi][1] = sAh[r1 + tq];      // (row g+8,  k t)
          ah[mi][2] = sAh[r0 + tq + 4];  // (row g,    k t+4)
          ah[mi][3] = sAh[r1 + tq + 4];  // (row g+8,  k t+4)
          al[mi][0] = sAl[r0 + tq];
          al[mi][1] = sAl[r1 + tq];
          al[mi][2] = sAl[r0 + tq + 4];
          al[mi][3] = sAl[r1 + tq + 4];
        }
        uint32_t bh[4][2], bl[4][2];
#pragma unroll
        for (int ni = 0; ni < 4; ni++) {
          const int c = bbase + (wn * 32 + ni * 8 + g) * 9;
          bh[ni][0] = sBh[c + tq];      // (k t,   n g)
          bh[ni][1] = sBh[c + tq + 4];  // (k t+4, n g)
          bl[ni][0] = sBl[c + tq];
          bl[ni][1] = sBl[c + tq + 4];
        }
#pragma unroll
        for (int mi = 0; mi < 2; mi++)
#pragma unroll
          for (int ni = 0; ni < 4; ni++) {
            mma_tf32(d[mi][ni], ah[mi], bh[ni]);  // hi*hi
            mma_tf32(d[mi][ni], al[mi], bh[ni]);  // lo*hi
            mma_tf32(d[mi][ni], ah[mi], bl[ni]);  // hi*lo
          }
      }
    }

    // Epilogue: D rows g (d0,d1) and g+8 (d2,d3), cols 2t, 2t+1.
#pragma unroll
    for (int mi = 0; mi < 2; mi++) {
      const int orow = o0 + wm * 32 + mi * 16 + g;
      const float u0 = g_u[orow];
      const float u1 = g_u[orow + 8];
#pragma unroll
      for (int ni = 0; ni < 4; ni++) {
        const int pc = p0 + wn * 32 + ni * 8 + 2 * tq;
        float2 v0, v1;
        v0.x = d[mi][ni][0] + u0;
        v0.y = d[mi][ni][1] + u0;
        v1.x = d[mi][ni][2] + u1;
        v1.y = d[mi][ni][3] + u1;
        *(float2*)(Go + (size_t)orow * HW + pc) = v0;
        *(float2*)(Go + (size_t)(orow + 8) * HW + pc) = v1;
      }
    }
  }

  // ===== Reset counters for next replay =====
  __syncthreads();
  if (tid == 0) {
    const unsigned dd = atomicAdd(&g_done, 1u);
    if (dd == 255u) {
      atomicExch(&g_gate, 0u);
      atomicExch(&g_done, 0u);
    }
  }
}

// ---------------------------------------------------------------------------
// Kernel 2: sparse local attention (R8 verbatim — proven 37.5 us).
// ---------------------------------------------------------------------------
#define SST 36
#define ABUF (256 * SST)

__device__ __forceinline__ void halo_fetch(const float* __restrict__ P,
                                           int base, int cg0, bool hin,
                                           int haddr, float4* hv) {
#pragma unroll
  for (int j = 0; j < 4; j++) {
    const int c = base + (cg0 + 2 * j) * 4;
    float4 v;
    v.x = hin ? P[(size_t)(c + 0) * HW + haddr] : 0.f;
    v.y = hin ? P[(size_t)(c + 1) * HW + haddr] : 0.f;
    v.z = hin ? P[(size_t)(c + 2) * HW + haddr] : 0.f;
    v.w = hin ? P[(size_t)(c + 3) * HW + haddr] : 0.f;
    hv[j] = v;
  }
}
__device__ __forceinline__ void halo_store(float* bufq, int cg0,
                                           const float4* hv) {
#pragma unroll
  for (int j = 0; j < 4; j++)
    *(float4*)(bufq + (cg0 + 2 * j) * 4) = hv[j];
}

__global__ __launch_bounds__(512) void psla_attn(const float* __restrict__ Ft,
                                                 float* __restrict__ out) {
  extern __shared__ float sm[];
  constexpr int kdx[NK] = {0, -1,-1,-1,0,0,1,1,1, -2,-2,-2,0,0,2,2,2,
                           -3,-3,-3,0,0,3,3,3, -4,-4,-4,0,0,4,4,4};
  constexpr int kdy[NK] = {0, -1,0,1,-1,1,-1,0,1, -2,0,2,-2,2,-2,0,2,
                           -3,0,3,-3,3,-3,0,3, -4,0,4,-4,4,-4,0,4};

  const int b = blockIdx.z;
  const int gx0 = blockIdx.x * 8, gy0 = blockIdx.y * 8;
  const int tid = threadIdx.x;
  const int px = tid >> 3, sub = tid & 7;
  const int lx = px & 7, ly = px >> 3;
  const int gx = gx0 + lx, gy = gy0 + ly;
  const int gp = gy * WW + gx;

  const float* Gb  = g_G + (size_t)b * CCH * HW;
  const float* Ftb = Ft + (size_t)b * CCH * HW;

  const int q   = tid & 255;
  const int cg0 = tid >> 8;  // 0 or 1
  const int hy = gy0 - 4 + (q >> 4);
  const int hx = gx0 - 4 + (q & 15);
  const bool hin = ((unsigned)hy < HH) && ((unsigned)hx < WW);
  const int haddr = hy * WW + hx;
  float* const myq0 = sm + q * SST;

  const float* const cbase = sm + ((ly + 4) * 16 + (lx + 4)) * SST + sub * 4;

  unsigned long long vmask = 0ull;
#pragma unroll
  for (int k = 0; k < NK; k++)
    if ((unsigned)(gy + kdx[k]) < HH && (unsigned)(gx + kdy[k]) < WW)
      vmask |= (1ull << k);

  float aff[NK];
#pragma unroll
  for (int k = 0; k < NK; k++) aff[k] = 0.f;

  float4 h[2][4];
  float e[3][4];

  // ==== Phase A: aff[k] = <G(p), Ft(p+delta_k)> ====
  halo_fetch(Ftb, 0, cg0, hin, haddr, h[0]);
#pragma unroll
  for (int cc = 0; cc < 4; cc++) e[0][cc] = Gb[(size_t)(sub * 4 + cc) * HW + gp];
  halo_fetch(Ftb, 32, cg0, hin, haddr, h[1]);
#pragma unroll
  for (int cc = 0; cc < 4; cc++)
    e[1][cc] = Gb[(size_t)(32 + sub * 4 + cc) * HW + gp];
  halo_store(myq0, cg0, h[0]);  // buf 0 <- chunk 0
  __syncthreads();

#pragma unroll
  for (int c0 = 0; c0 < 8; c0++) {
    if (c0 < 6) {
      const int base = (c0 + 2) * 32;
      halo_fetch(Ftb, base, cg0, hin, haddr, h[c0 & 1]);
#pragma unroll
      for (int cc = 0; cc < 4; cc++)
        e[(c0 + 2) % 3][cc] = Gb[(size_t)(base + sub * 4 + cc) * HW + gp];
    }
    const float* bp = cbase + (c0 % 3) * ABUF;
    const float e0 = e[c0 % 3][0], e1 = e[c0 % 3][1];
    const float e2 = e[c0 % 3][2], e3 = e[c0 % 3][3];
#pragma unroll
    for (int k = 0; k < NK; k++) {
      const float4 v = *(const float4*)(bp + (kdx[k] * 16 + kdy[k]) * SST);
      float s = fmaf(e0, v.x, 0.f);
      s = fmaf(e1, v.y, s);
      s = fmaf(e2, v.z, s);
      s = fmaf(e3, v.w, s);
      aff[k] += s;
    }
    if (c0 < 7)
      halo_store(myq0 + ((c0 + 1) % 3) * ABUF, cg0, h[(c0 + 1) & 1]);
    __syncthreads();
  }

  // Reduce partial dots across the 8 channel-subgroups (lanes xor 1,2,4).
#pragma unroll
  for (int k = 0; k < NK; k++) {
    aff[k] += __shfl_xor_sync(0xffffffffu, aff[k], 1);
    aff[k] += __shfl_xor_sync(0xffffffffu, aff[k], 2);
    aff[k] += __shfl_xor_sync(0xffffffffu, aff[k], 4);
  }

  // ==== Softmax over valid offsets (k=0 always valid) ====
  float m = aff[0];
#pragma unroll
  for (int k = 1; k < NK; k++)
    if ((vmask >> k) & 1ull) m = fmaxf(m, aff[k]);
  float ssum = 0.f;
#pragma unroll
  for (int k = 0; k < NK; k++) {
    if ((vmask >> k) & 1ull) {
      aff[k] = __expf(aff[k] - m);
      ssum += aff[k];
    } else {
      aff[k] = 0.f;
    }
  }
  const float inv = 1.f / ssum;
#pragma unroll
  for (int k = 0; k < NK; k++) aff[k] *= inv;

  // ==== Phase B: out(c,p) = sum_k w_k * Ft(c, p + delta_k), FFMA2 ====
  halo_fetch(Ftb, 0, cg0, hin, haddr, h[0]);
  halo_fetch(Ftb, 32, cg0, hin, haddr, h[1]);
  halo_store(myq0, cg0, h[0]);
  __syncthreads();

#pragma unroll
  for (int c0 = 0; c0 < 8; c0++) {
    if (c0 < 6)
      halo_fetch(Ftb, (c0 + 2) * 32, cg0, hin, haddr, h[c0 & 1]);

    const float* bp = cbase + (c0 % 3) * ABUF;
    unsigned long long a01 = 0ull, a23 = 0ull;
#pragma unroll
    for (int k = 0; k < NK; k++) {
      const ulonglong2 vv =
          *(const ulonglong2*)(bp + (kdx[k] * 16 + kdy[k]) * SST);
      const unsigned long long wk2 = pack2_bcast(aff[k]);
      a01 = ffma2(wk2, vv.x, a01);
      a23 = ffma2(wk2, vv.y, a23);
    }
    float o0, o1, o2, o3;
    unpack2(a01, o0, o1);
    unpack2(a23, o2, o3);
    float* op = out + (size_t)(b * CCH + c0 * 32 + sub * 4) * HW + gp;
    op[0] = o0;
    op[HW] = o1;
    op[2 * HW] = o2;
    op[3 * HW] = o3;

    if (c0 < 7)
      halo_store(myq0 + ((c0 + 1) % 3) * ABUF, cg0, h[(c0 + 1) & 1]);
    __syncthreads();
  }
}

// ---------------------------------------------------------------------------
extern "C" void kernel_launch(void* const* d_in, const int* in_sizes, int n_in,
                              void* d_out, int out_size) {
  const float* Ft  = (const float*)d_in[0];
  const float* Fte = (const float*)d_in[1];
  const float* Wf  = (const float*)d_in[2];
  // d_in[3] = bf: cancels in the softmax (constant in k) — unused.
  const float* Wg  = (const float*)d_in[4];
  const float* bg  = (const float*)d_in[5];
  float* out = (float*)d_out;

  cudaFuncSetAttribute(psla_gemm_fused,
                       cudaFuncAttributeMaxDynamicSharedMemorySize, FUSED_SMEM);
  const int attn_smem = 3 * ABUF * (int)sizeof(float);  // 110592 B
  cudaFuncSetAttribute(psla_attn, cudaFuncAttributeMaxDynamicSharedMemorySize,
                       attn_smem);

  psla_gemm_fused<<<256, 256, FUSED_SMEM>>>(Fte, Wf, Wg, bg);

  dim3 ga(8, 8, 2);  // W/8, H/8, B
  psla_attn<<<ga, 512, attn_smem>>>(Ft, out);
}

// round 17
// speedup vs baseline: 1.0709x; 1.0709x over previous
#include <cuda_runtime.h>
#include <cstdint>

#define HH 64
#define WW 64
#define HW 4096
#define CCH 256
#define NK 33

// Scratch
__device__ float g_G[2u * 256u * 4096u];  // G[b][d][p] = Mt @ Fte + u
__device__ float g_M[256u * 256u];        // Mt[d][c]
__device__ float g_u[256u];               // u[d]
__device__ unsigned g_gate = 0u;
__device__ unsigned g_done = 0u;

// ---------------------------------------------------------------------------
// f32x2 packed helpers (FFMA2 via PTX fma.rn.f32x2)
// ---------------------------------------------------------------------------
__device__ __forceinline__ unsigned long long pack2_bcast(float x) {
  unsigned long long r;
  asm("mov.b64 %0, {%1, %1};" : "=l"(r) : "f"(x));
  return r;
}
__device__ __forceinline__ unsigned long long ffma2(unsigned long long a,
                                                    unsigned long long b,
                                                    unsigned long long c) {
  unsigned long long d;
  asm("fma.rn.f32x2 %0, %1, %2, %3;" : "=l"(d) : "l"(a), "l"(b), "l"(c));
  return d;
}
__device__ __forceinline__ void unpack2(unsigned long long v, float& lo, float& hi) {
  asm("mov.b64 {%0, %1}, %2;" : "=f"(lo), "=f"(hi) : "l"(v));
}

// ---------------------------------------------------------------------------
// Kernel 1 (fused): prep (Mt, u) + G = Mt @ Fte + u.
// v3: 256 CTAs, GEMM tile 128o x 64p, 2 CTAs/SM, kc=16 DOUBLE-BUFFERED
// (one barrier per chunk; 16 chunks instead of 32x2 barriers).
// ---------------------------------------------------------------------------
#define PSTR 36
#define FUSED_SMEM (2 * 256 * PSTR * (int)sizeof(float))  // 73728 B

__global__ __launch_bounds__(256, 2) void psla_gemm_fused(
    const float* __restrict__ Fte, const float* __restrict__ Wf,
    const float* __restrict__ Wg, const float* __restrict__ bg) {
  extern __shared__ float dsm[];
  const int bid = blockIdx.x;
  const int tid = threadIdx.x;

  // ===== Phase 0: prep (first 65 CTAs) =====
  if (bid < 64) {
    float (*sg)[PSTR] = (float (*)[PSTR])dsm;
    float (*sf)[PSTR] = (float (*)[PSTR])(dsm + 256 * PSTR);
    const int c0 = (bid & 7) * 32;
    const int d0 = (bid >> 3) * 32;

    float4 ga[8], fa[8];
#pragma unroll
    for (int j = 0; j < 8; j++) {
      ga[j] = *(const float4*)(Wg + (size_t)tid * 256 + c0 + 4 * j);
      fa[j] = *(const float4*)(Wf + (size_t)tid * 256 + d0 + 4 * j);
    }
#pragma unroll
    for (int j = 0; j < 8; j++) {
      *(float4*)&sg[tid][4 * j] = ga[j];
      *(float4*)&sf[tid][4 * j] = fa[j];
    }
    __syncthreads();

    const int tc = (tid & 15) * 2, td = (tid >> 4) * 2;
    float a00 = 0.f, a01 = 0.f, a10 = 0.f, a11 = 0.f;
#pragma unroll 8
    for (int kk = 0; kk < 256; kk++) {
      const float2 g2 = *(const float2*)&sg[kk][tc];
      const float2 f2 = *(const float2*)&sf[kk][td];
      a00 = fmaf(f2.x, g2.x, a00);
      a01 = fmaf(f2.x, g2.y, a01);
      a10 = fmaf(f2.y, g2.x, a10);
      a11 = fmaf(f2.y, g2.y, a11);
    }
    g_M[(size_t)(d0 + td + 0) * 256 + c0 + tc + 0] = a00;
    g_M[(size_t)(d0 + td + 0) * 256 + c0 + tc + 1] = a01;
    g_M[(size_t)(d0 + td + 1) * 256 + c0 + tc + 0] = a10;
    g_M[(size_t)(d0 + td + 1) * 256 + c0 + tc + 1] = a11;

    __threadfence();
    __syncthreads();
    if (tid == 0) atomicAdd(&g_gate, 1u);
  } else if (bid == 64) {
    float s0 = 0.f, s1 = 0.f, s2 = 0.f, s3 = 0.f;
#pragma unroll
    for (int o = 0; o < 256; o += 4) {
      s0 = fmaf(bg[o + 0], Wf[(o + 0) * 256 + tid], s0);
      s1 = fmaf(bg[o + 1], Wf[(o + 1) * 256 + tid], s1);
      s2 = fmaf(bg[o + 2], Wf[(o + 2) * 256 + tid], s2);
      s3 = fmaf(bg[o + 3], Wf[(o + 3) * 256 + tid], s3);
    }
    g_u[tid] = (s0 + s1) + (s2 + s3);
    __threadfence();
    __syncthreads();
    if (tid == 0) atomicAdd(&g_gate, 1u);
  }

  // ===== Gate =====
  if (tid == 0) {
    while (atomicAdd(&g_gate, 0u) < 65u) __nanosleep(64);
  }
  __syncthreads();

  // ===== Phase 1: GEMM tile 128 o x 64 p, kc=16, double-buffered =====
  {
    float* sA = dsm;                 // [2][16][132]
    float* sB = dsm + 2 * 16 * 132;  // [2][16][68]

    const int rest = bid >> 6;  // 0..3
    const int b = rest & 1;
    const int o0 = (rest >> 1) * 128;
    const int p0 = (bid & 63) * 64;
    const float* X = Fte + (size_t)b * CCH * HW;
    float* Go = g_G + (size_t)b * CCH * HW;

    const int tx = tid & 15, ty = tid >> 4;  // 16 x 16 thread grid

    unsigned long long acc2[8][2];
#pragma unroll
    for (int i = 0; i < 8; i++) {
      acc2[i][0] = 0ull;
      acc2[i][1] = 0ull;
    }

    // Loaders (kc=16): A rows o = tid>>1, k-group (tid&1)*8 (2 float4);
    //                  B rows k = tid>>4, p-group (tid&15)*4 (1 float4).
    const int ao = tid >> 1, akg = (tid & 1) * 8;
    const int bk = tid >> 4, bp4 = (tid & 15) * 4;

    // Preload chunk 0 into buffer 0.
    float4 av0 = *(const float4*)(g_M + (size_t)(o0 + ao) * CCH + akg);
    float4 av1 = *(const float4*)(g_M + (size_t)(o0 + ao) * CCH + akg + 4);
    float4 bv = *(const float4*)(X + (size_t)bk * HW + p0 + bp4);
    {
      float* A0 = sA;
      A0[(akg + 0) * 132 + ao] = av0.x;
      A0[(akg + 1) * 132 + ao] = av0.y;
      A0[(akg + 2) * 132 + ao] = av0.z;
      A0[(akg + 3) * 132 + ao] = av0.w;
      A0[(akg + 4) * 132 + ao] = av1.x;
      A0[(akg + 5) * 132 + ao] = av1.y;
      A0[(akg + 6) * 132 + ao] = av1.z;
      A0[(akg + 7) * 132 + ao] = av1.w;
      *(float4*)&sB[bk * 68 + bp4] = bv;
    }
    __syncthreads();

    for (int t = 0; t < 16; t++) {
      if (t < 15) {
        const int k0 = (t + 1) * 16;
        av0 = *(const float4*)(g_M + (size_t)(o0 + ao) * CCH + k0 + akg);
        av1 = *(const float4*)(g_M + (size_t)(o0 + ao) * CCH + k0 + akg + 4);
        bv = *(const float4*)(X + (size_t)(k0 + bk) * HW + p0 + bp4);
      }
      const float* cA = sA + (t & 1) * 16 * 132;
      const float* cB = sB + (t & 1) * 16 * 68;
#pragma unroll
      for (int kk = 0; kk < 16; kk++) {
        float a[8];
        *(float4*)&a[0] = *(const float4*)&cA[kk * 132 + ty * 8];
        *(float4*)&a[4] = *(const float4*)&cA[kk * 132 + ty * 8 + 4];
        unsigned long long b2[2];
        ulonglong2 bl = *(const ulonglong2*)&cB[kk * 68 + tx * 4];
        b2[0] = bl.x;
        b2[1] = bl.y;
        unsigned long long a2[8];
#pragma unroll
        for (int i = 0; i < 8; i++) a2[i] = pack2_bcast(a[i]);
#pragma unroll
        for (int i = 0; i < 8; i++) {
          acc2[i][0] = ffma2(a2[i], b2[0], acc2[i][0]);
          acc2[i][1] = ffma2(a2[i], b2[1], acc2[i][1]);
        }
      }
      if (t < 15) {
        float* nA = sA + ((t & 1) ^ 1) * 16 * 132;
        float* nB = sB + ((t & 1) ^ 1) * 16 * 68;
        nA[(akg + 0) * 132 + ao] = av0.x;
        nA[(akg + 1) * 132 + ao] = av0.y;
        nA[(akg + 2) * 132 + ao] = av0.z;
        nA[(akg + 3) * 132 + ao] = av0.w;
        nA[(akg + 4) * 132 + ao] = av1.x;
        nA[(akg + 5) * 132 + ao] = av1.y;
        nA[(akg + 6) * 132 + ao] = av1.z;
        nA[(akg + 7) * 132 + ao] = av1.w;
        *(float4*)&nB[bk * 68 + bp4] = bv;
      }
      __syncthreads();
    }

#pragma unroll
    for (int i = 0; i < 8; i++) {
      const int o = o0 + ty * 8 + i;
      const float bvv = g_u[o];
      float r[4];
      unpack2(acc2[i][0], r[0], r[1]);
      unpack2(acc2[i][1], r[2], r[3]);
      float4 v;
      v.x = r[0] + bvv;
      v.y = r[1] + bvv;
      v.z = r[2] + bvv;
      v.w = r[3] + bvv;
      *(float4*)(Go + (size_t)o * HW + p0 + tx * 4) = v;
    }
  }

  // ===== Reset counters for next replay (last of 256 CTAs) =====
  __syncthreads();
  if (tid == 0) {
    const unsigned d = atomicAdd(&g_done, 1u);
    if (d == 255u) {
      atomicExch(&g_gate, 0u);
      atomicExch(&g_done, 0u);
    }
  }
}

// ---------------------------------------------------------------------------
// Kernel 2: sparse local attention (R8 verbatim — proven 37.5 us).
// 8x8 pixel tile, 512 threads, triple-buffered smem halo [3][256][36].
// ---------------------------------------------------------------------------
#define SST 36
#define ABUF (256 * SST)

__device__ __forceinline__ void halo_fetch(const float* __restrict__ P,
                                           int base, int cg0, bool hin,
                                           int haddr, float4* hv) {
#pragma unroll
  for (int j = 0; j < 4; j++) {
    const int c = base + (cg0 + 2 * j) * 4;
    float4 v;
    v.x = hin ? P[(size_t)(c + 0) * HW + haddr] : 0.f;
    v.y = hin ? P[(size_t)(c + 1) * HW + haddr] : 0.f;
    v.z = hin ? P[(size_t)(c + 2) * HW + haddr] : 0.f;
    v.w = hin ? P[(size_t)(c + 3) * HW + haddr] : 0.f;
    hv[j] = v;
  }
}
__device__ __forceinline__ void halo_store(float* bufq, int cg0,
                                           const float4* hv) {
#pragma unroll
  for (int j = 0; j < 4; j++)
    *(float4*)(bufq + (cg0 + 2 * j) * 4) = hv[j];
}

__global__ __launch_bounds__(512) void psla_attn(const float* __restrict__ Ft,
                                                 float* __restrict__ out) {
  extern __shared__ float sm[];
  constexpr int kdx[NK] = {0, -1,-1,-1,0,0,1,1,1, -2,-2,-2,0,0,2,2,2,
                           -3,-3,-3,0,0,3,3,3, -4,-4,-4,0,0,4,4,4};
  constexpr int kdy[NK] = {0, -1,0,1,-1,1,-1,0,1, -2,0,2,-2,2,-2,0,2,
                           -3,0,3,-3,3,-3,0,3, -4,0,4,-4,4,-4,0,4};

  const int b = blockIdx.z;
  const int gx0 = blockIdx.x * 8, gy0 = blockIdx.y * 8;
  const int tid = threadIdx.x;
  const int px = tid >> 3, sub = tid & 7;
  const int lx = px & 7, ly = px >> 3;
  const int gx = gx0 + lx, gy = gy0 + ly;
  const int gp = gy * WW + gx;

  const float* Gb  = g_G + (size_t)b * CCH * HW;
  const float* Ftb = Ft + (size_t)b * CCH * HW;

  const int q   = tid & 255;
  const int cg0 = tid >> 8;  // 0 or 1
  const int hy = gy0 - 4 + (q >> 4);
  const int hx = gx0 - 4 + (q & 15);
  const bool hin = ((unsigned)hy < HH) && ((unsigned)hx < WW);
  const int haddr = hy * WW + hx;
  float* const myq0 = sm + q * SST;

  const float* const cbase = sm + ((ly + 4) * 16 + (lx + 4)) * SST + sub * 4;

  unsigned long long vmask = 0ull;
#pragma unroll
  for (int k = 0; k < NK; k++)
    if ((unsigned)(gy + kdx[k]) < HH && (unsigned)(gx + kdy[k]) < WW)
      vmask |= (1ull << k);

  float aff[NK];
#pragma unroll
  for (int k = 0; k < NK; k++) aff[k] = 0.f;

  float4 h[2][4];
  float e[3][4];

  // ==== Phase A: aff[k] = <G(p), Ft(p+delta_k)> ====
  halo_fetch(Ftb, 0, cg0, hin, haddr, h[0]);
#pragma unroll
  for (int cc = 0; cc < 4; cc++) e[0][cc] = Gb[(size_t)(sub * 4 + cc) * HW + gp];
  halo_fetch(Ftb, 32, cg0, hin, haddr, h[1]);
#pragma unroll
  for (int cc = 0; cc < 4; cc++)
    e[1][cc] = Gb[(size_t)(32 + sub * 4 + cc) * HW + gp];
  halo_store(myq0, cg0, h[0]);  // buf 0 <- chunk 0
  __syncthreads();

#pragma unroll
  for (int c0 = 0; c0 < 8; c0++) {
    if (c0 < 6) {
      const int base = (c0 + 2) * 32;
      halo_fetch(Ftb, base, cg0, hin, haddr, h[c0 & 1]);
#pragma unroll
      for (int cc = 0; cc < 4; cc++)
        e[(c0 + 2) % 3][cc] = Gb[(size_t)(base + sub * 4 + cc) * HW + gp];
    }
    const float* bp = cbase + (c0 % 3) * ABUF;
    const float e0 = e[c0 % 3][0], e1 = e[c0 % 3][1];
    const float e2 = e[c0 % 3][2], e3 = e[c0 % 3][3];
#pragma unroll
    for (int k = 0; k < NK; k++) {
      const float4 v = *(const float4*)(bp + (kdx[k] * 16 + kdy[k]) * SST);
      float s = fmaf(e0, v.x, 0.f);
      s = fmaf(e1, v.y, s);
      s = fmaf(e2, v.z, s);
      s = fmaf(e3, v.w, s);
      aff[k] += s;
    }
    if (c0 < 7)
      halo_store(myq0 + ((c0 + 1) % 3) * ABUF, cg0, h[(c0 + 1) & 1]);
    __syncthreads();
  }

  // Reduce partial dots across the 8 channel-subgroups (lanes xor 1,2,4).
#pragma unroll
  for (int k = 0; k < NK; k++) {
    aff[k] += __shfl_xor_sync(0xffffffffu, aff[k], 1);
    aff[k] += __shfl_xor_sync(0xffffffffu, aff[k], 2);
    aff[k] += __shfl_xor_sync(0xffffffffu, aff[k], 4);
  }

  // ==== Softmax over valid offsets (k=0 always valid) ====
  float m = aff[0];
#pragma unroll
  for (int k = 1; k < NK; k++)
    if ((vmask >> k) & 1ull) m = fmaxf(m, aff[k]);
  float ssum = 0.f;
#pragma unroll
  for (int k = 0; k < NK; k++) {
    if ((vmask >> k) & 1ull) {
      aff[k] = __expf(aff[k] - m);
      ssum += aff[k];
    } else {
      aff[k] = 0.f;
    }
  }
  const float inv = 1.f / ssum;
#pragma unroll
  for (int k = 0; k < NK; k++) aff[k] *= inv;

  // ==== Phase B: out(c,p) = sum_k w_k * Ft(c, p + delta_k), FFMA2 ====
  halo_fetch(Ftb, 0, cg0, hin, haddr, h[0]);
  halo_fetch(Ftb, 32, cg0, hin, haddr, h[1]);
  halo_store(myq0, cg0, h[0]);
  __syncthreads();

#pragma unroll
  for (int c0 = 0; c0 < 8; c0++) {
    if (c0 < 6)
      halo_fetch(Ftb, (c0 + 2) * 32, cg0, hin, haddr, h[c0 & 1]);

    const float* bp = cbase + (c0 % 3) * ABUF;
    unsigned long long a01 = 0ull, a23 = 0ull;
#pragma unroll
    for (int k = 0; k < NK; k++) {
      const ulonglong2 vv =
          *(const ulonglong2*)(bp + (kdx[k] * 16 + kdy[k]) * SST);
      const unsigned long long wk2 = pack2_bcast(aff[k]);
      a01 = ffma2(wk2, vv.x, a01);
      a23 = ffma2(wk2, vv.y, a23);
    }
    float o0, o1, o2, o3;
    unpack2(a01, o0, o1);
    unpack2(a23, o2, o3);
    float* op = out + (size_t)(b * CCH + c0 * 32 + sub * 4) * HW + gp;
    op[0] = o0;
    op[HW] = o1;
    op[2 * HW] = o2;
    op[3 * HW] = o3;

    if (c0 < 7)
      halo_store(myq0 + ((c0 + 1) % 3) * ABUF, cg0, h[(c0 + 1) & 1]);
    __syncthreads();
  }
}

// ---------------------------------------------------------------------------
extern "C" void kernel_launch(void* const* d_in, const int* in_sizes, int n_in,
                              void* d_out, int out_size) {
  const float* Ft  = (const float*)d_in[0];
  const float* Fte = (const float*)d_in[1];
  const float* Wf  = (const float*)d_in[2];
  // d_in[3] = bf: cancels in the softmax (constant in k) — unused.
  const float* Wg  = (const float*)d_in[4];
  const float* bg  = (const float*)d_in[5];
  float* out = (float*)d_out;

  cudaFuncSetAttribute(psla_gemm_fused,
                       cudaFuncAttributeMaxDynamicSharedMemorySize, FUSED_SMEM);
  const int attn_smem = 3 * ABUF * (int)sizeof(float);  // 110592 B
  cudaFuncSetAttribute(psla_attn, cudaFuncAttributeMaxDynamicSharedMemorySize,
                       attn_smem);

  psla_gemm_fused<<<256, 256, FUSED_SMEM>>>(Fte, Wf, Wg, bg);

  dim3 ga(8, 8, 2);  // W/8, H/8, B
  psla_attn<<<ga, 512, attn_smem>>>(Ft, out);
}